// round 12
// baseline (speedup 1.0000x reference)
#include <cuda_runtime.h>
#include <math.h>

#define FULLM 0xffffffffu
#define NQ 10
#define WPB 4
#define THREADS (WPB * 32)

typedef unsigned long long u64;

// ---- precomputed weight-only tables (built once per launch) -----------------
__device__ float4 g_Us[NQ];       // layer-0 U (u00.x,u00.y,u01.x,u01.y)
__device__ float2 g_RYp[2 * NQ];  // (cos b/2, sin b/2) layers 1,2
__device__ float4 g_DgA[512];     // diag Rz(a1)
__device__ float4 g_DgD[512];     // diag Rz(c1)*Rz(a2)

// ---- f32x2 packed helpers --------------------------------------------------
__device__ __forceinline__ u64 bc2(float s) {
    u64 d; unsigned r = __float_as_uint(s);
    asm("mov.b64 %0, {%1, %1};" : "=l"(d) : "r"(r));
    return d;
}
__device__ __forceinline__ u64 pk2(float lo, float hi) {
    u64 d; unsigned a = __float_as_uint(lo), b = __float_as_uint(hi);
    asm("mov.b64 %0, {%1, %2};" : "=l"(d) : "r"(a), "r"(b));
    return d;
}
__device__ __forceinline__ void up2(u64 a, float& lo, float& hi) {
    unsigned l, h;
    asm("mov.b64 {%0, %1}, %2;" : "=r"(l), "=r"(h) : "l"(a));
    lo = __uint_as_float(l); hi = __uint_as_float(h);
}
__device__ __forceinline__ u64 fma2(u64 a, u64 b, u64 c) {
    u64 d;
    asm("fma.rn.f32x2 %0, %1, %2, %3;" : "=l"(d) : "l"(a), "l"(b), "l"(c));
    return d;
}
__device__ __forceinline__ u64 mul2(u64 a, u64 b) {
    u64 d;
    asm("mul.rn.f32x2 %0, %1, %2;" : "=l"(d) : "l"(a), "l"(b));
    return d;
}
__device__ __forceinline__ u64 add2(u64 a, u64 b) {
    u64 d;
    asm("add.rn.f32x2 %0, %1, %2;" : "=l"(d) : "l"(a), "l"(b));
    return d;
}
__device__ __forceinline__ u64 swp2(u64 a) {
    unsigned l, h;
    asm("mov.b64 {%0, %1}, %2;" : "=r"(l), "=r"(h) : "l"(a));
    u64 d;
    asm("mov.b64 %0, {%1, %2};" : "=l"(d) : "r"(h), "r"(l));
    return d;
}
__device__ __forceinline__ u64 shflx2(u64 a, int mask) {
    unsigned l, h;
    asm("mov.b64 {%0, %1}, %2;" : "=r"(l), "=r"(h) : "l"(a));
    l = __shfl_xor_sync(FULLM, l, mask);
    h = __shfl_xor_sync(FULLM, h, mask);
    u64 d;
    asm("mov.b64 %0, {%1, %2};" : "=l"(d) : "r"(l), "r"(h));
    return d;
}
__device__ __forceinline__ float2 cmulf(float2 a, float2 b) {
    return make_float2(a.x * b.x - a.y * b.y, a.x * b.y + a.y * b.x);
}

// ---- Ry gate primitives (real rotations) ------------------------------------
// State: amp index s = (lane<<5)|(m<<1)|h ; pX/pY hold (h=0,h=1) packed.

__device__ __forceinline__ void lane_gateR(u64 pX[16], u64 pY[16],
                                           int xorMask, bool hi,
                                           float cb, float sb) {
    const float t = hi ? sb : -sb;
    const u64 C = bc2(cb), T = bc2(t);
#pragma unroll
    for (int m = 0; m < 16; m++) {
        u64 bx = shflx2(pX[m], xorMask), by = shflx2(pY[m], xorMask);
        pX[m] = fma2(C, pX[m], mul2(T, bx));
        pY[m] = fma2(C, pY[m], mul2(T, by));
    }
}

template<int MXOR>
__device__ __forceinline__ void cross_gateR(u64 pX[16], u64 pY[16],
                                            int laneXor, bool hi,
                                            float cb, float sb) {
    const float t = hi ? sb : -sb;
    const u64 C = bc2(cb), T = bc2(t);
#pragma unroll
    for (int m0 = 0; m0 < 16; m0++) {
        if (m0 & MXOR) continue;
        const int m1 = m0 | MXOR;
        u64 b0x = shflx2(pX[m1], laneXor), b0y = shflx2(pY[m1], laneXor);
        u64 b1x = shflx2(pX[m0], laneXor), b1y = shflx2(pY[m0], laneXor);
        pX[m0] = fma2(C, pX[m0], mul2(T, b0x));
        pY[m0] = fma2(C, pY[m0], mul2(T, b0y));
        pX[m1] = fma2(C, pX[m1], mul2(T, b1x));
        pY[m1] = fma2(C, pY[m1], mul2(T, b1y));
    }
}

template<int MXOR> struct Anch {
    static const int v = (MXOR >= 8) ? 8 : (MXOR >= 4) ? 4 : (MXOR >= 2) ? 2 : 1;
};

template<int MXOR, int CLS>
__device__ __forceinline__ void reg_gateR(u64 pX[16], u64 pY[16], bool sb_sel,
                                          float cb, float sbv) {
    const float x1 = sb_sel ? sbv : -sbv;
    const u64 C = bc2(cb), T = bc2(x1), Tn = bc2(-x1);
#pragma unroll
    for (int mA = 0; mA < 16; mA++) {
        if (mA & Anch<MXOR>::v) continue;
        const int mB = mA ^ MXOR;
        const bool cls = __popc(mA & CLS) & 1;
        const u64 tp = cls ? Tn : T;
        const u64 tn = cls ? T : Tn;
        u64 Ax = pX[mA], Ay = pY[mA], Bx = pX[mB], By = pY[mB];
        pX[mA] = fma2(C, Ax, mul2(tp, Bx));
        pY[mA] = fma2(C, Ay, mul2(tp, By));
        pX[mB] = fma2(C, Bx, mul2(tn, Ax));
        pY[mB] = fma2(C, By, mul2(tn, Ay));
    }
}

template<int MXOR, int CLS>
__device__ __forceinline__ void hcross_gateR(u64 pX[16], u64 pY[16], bool sb_sel,
                                             float cb, float sbv) {
    const float x1 = sb_sel ? sbv : -sbv;
    const u64 C = bc2(cb), T = bc2(x1), Tn = bc2(-x1);
#pragma unroll
    for (int mA = 0; mA < 16; mA++) {
        if (mA & Anch<MXOR>::v) continue;
        const int mB = mA ^ MXOR;
        const bool cls = __popc(mA & CLS) & 1;
        const u64 tp = cls ? Tn : T;
        const u64 tn = cls ? T : Tn;
        u64 Ax = pX[mA], Ay = pY[mA];
        u64 Bx = swp2(pX[mB]), By = swp2(pY[mB]);
        u64 nBx = fma2(C, Bx, mul2(tn, Ax));
        u64 nBy = fma2(C, By, mul2(tn, Ay));
        pX[mA] = fma2(C, Ax, mul2(tp, Bx));
        pY[mA] = fma2(C, Ay, mul2(tp, By));
        pX[mB] = swp2(nBx); pY[mB] = swp2(nBy);
    }
}

template<int CLS>
__device__ __forceinline__ void pair_gateR(u64 pX[16], u64 pY[16], bool sb_sel,
                                           float cb, float sbv) {
    const float x1 = sb_sel ? sbv : -sbv;
    const u64 C = bc2(cb);
    const u64 OX = pk2(x1, -x1), OXn = pk2(-x1, x1);
#pragma unroll
    for (int m = 0; m < 16; m++) {
        const bool s = __popc(m & CLS) & 1;
        u64 ox = s ? OXn : OX;
        u64 sx = swp2(pX[m]), sy = swp2(pY[m]);
        pX[m] = fma2(C, pX[m], mul2(ox, sx));
        pY[m] = fma2(C, pY[m], mul2(ox, sy));
    }
}

// diag entry: float4 (c0,s0,c1,s1) at index (m<<5)|lane
__device__ __forceinline__ void apply_diag(u64 pX[16], u64 pY[16],
                                           const float4* Dg, int lane) {
#pragma unroll
    for (int m = 0; m < 16; m++) {
        float4 f = Dg[(m << 5) | lane];
        u64 kx = pk2(f.x, f.z), ky = pk2(f.y, f.w), kyn = pk2(-f.y, -f.w);
        u64 nx = fma2(kx, pX[m], mul2(kyn, pY[m]));
        u64 ny = fma2(kx, pY[m], mul2(ky,  pX[m]));
        pX[m] = nx; pY[m] = ny;
    }
}

// ======= one-block precompute: gate params + diagonal tables =================
__global__ __launch_bounds__(128)
void precompute_kernel(const float* __restrict__ weights)
{
    __shared__ float thA1[10], thC1[10], thA2[10];
    __shared__ float LUT[6][32];

    const int tid = threadIdx.x;

    if (tid < NQ) {
        float a  = weights[tid * 3 + 0];
        float bb = weights[tid * 3 + 1];
        float c  = weights[tid * 3 + 2];
        float cb, sb;  __sincosf(0.5f * bb, &sb, &cb);
        float capc, sapc, camc, samc;
        __sincosf(0.5f * (a + c), &sapc, &capc);
        __sincosf(0.5f * (a - c), &samc, &camc);
        g_Us[tid] = make_float4(cb * capc, -cb * sapc, -sb * camc, -sb * samc);
    }
    if (tid >= 32 && tid < 52) {
        int g = tid - 32; int l = g / 10, w = g % 10;
        float bb = weights[((l + 1) * 10 + w) * 3 + 1];
        float sbv, cbv; __sincosf(0.5f * bb, &sbv, &cbv);
        g_RYp[g] = make_float2(cbv, sbv);
    }
    if (tid >= 64 && tid < 94) {
        int g = tid - 64; int arr = g / 10, k = g % 10; int w = 9 - k;
        float v = (arr == 0) ? weights[(10 + w) * 3 + 0]
                : (arr == 1) ? weights[(10 + w) * 3 + 2]
                             : weights[(20 + w) * 3 + 0];
        float* dst = (arr == 0) ? thA1 : (arr == 1) ? thC1 : thA2;
        dst[k] = 0.5f * v;
    }
    __syncthreads();

    for (int v = tid; v < 192; v += 128) {
        int tbl = v >> 5, idx = v & 31;
        const float* th = (tbl < 2) ? thA1 : (tbl < 4) ? thC1 : thA2;
        int base = (tbl & 1) * 5;
        float phi = 0.0f;
#pragma unroll
        for (int k = 0; k < 5; k++)
            phi += ((idx >> k) & 1) ? th[base + k] : -th[base + k];
        LUT[tbl][idx] = phi;
    }
    __syncthreads();

    for (int e = tid; e < 2048; e += 128) {
        int s = e & 1023;
        int t = s;
        t ^= t >> 1;  t ^= t >> 2;  t ^= t >> 4;  t ^= t >> 8;
        float phi;
        if (e < 1024) {
            phi = LUT[0][t & 31] + LUT[1][t >> 5];
        } else {
            int u = s;
            u ^= u >> 2;  u ^= u >> 4;  u ^= u >> 8;
            phi = LUT[2][t & 31] + LUT[3][t >> 5]
                + LUT[4][u & 31] + LUT[5][u >> 5];
        }
        float sn, cs; __sincosf(phi, &sn, &cs);
        int slot = (((s >> 1) & 15) << 5) | (s >> 5);
        float* dst = (float*)((e < 1024 ? g_DgA : g_DgD) + slot);
        dst[(s & 1) * 2 + 0] = cs;
        dst[(s & 1) * 2 + 1] = sn;
    }
}

// ======= main kernel =========================================================
__global__ __launch_bounds__(THREADS, 5)
void qgan_kernel(const float* __restrict__ z,
                 const float* __restrict__ W1, const float* __restrict__ b1,
                 const float* __restrict__ W2, const float* __restrict__ b2,
                 const float* __restrict__ W3, const float* __restrict__ b3,
                 float* __restrict__ out, int B)
{
    __shared__ float4 Us[NQ];
    __shared__ float2 RYp[2 * NQ];
    __shared__ float4 DgA4[512];
    __shared__ float4 DgD4[512];

    const int tid  = threadIdx.x;
    const int lane = tid & 31;
    const int wix  = tid >> 5;
    const int b    = blockIdx.x * WPB + wix;

    // copy precomputed tables into smem
#pragma unroll
    for (int i = tid; i < 512; i += THREADS) {
        DgA4[i] = g_DgA[i];
        DgD4[i] = g_DgD[i];
    }
    if (tid < NQ)                     Us[tid] = g_Us[tid];
    else if (tid >= 32 && tid < 52)   RYp[tid - 32] = g_RYp[tid - 32];
    __syncthreads();

    if (b >= B) return;

    float zc = 1.0f, zs = 0.0f;
    if (lane < NQ) {
        float zv = z[b * NQ + lane];
        zv = fminf(fmaxf(zv, -1.0f), 1.0f);
        __sincosf(0.5f * zv, &zs, &zc);
    }

    const bool pl  = __popc(lane) & 1;
    const bool pl2 = __popc(lane & 0b01010) & 1;
    const bool pl3 = __popc(lane & 0b10101) & 1;

    u64 pX[16], pY[16];

    // ======= layer 0 on |0..0>: product-state construction ==================
    {
        float2 P = make_float2(1.0f, 0.0f);
#pragma unroll
        for (int W = 0; W < 5; W++) {
            float4 u = Us[W];
            float c = __shfl_sync(FULLM, zc, W);
            float s = __shfl_sync(FULLM, zs, W);
            float2 A  = make_float2(u.x * c + u.z * s, u.y * c + u.w * s);
            float2 Bv = make_float2(u.x * s - u.z * c, u.w * c - u.y * s);
            float2 col = ((lane >> (4 - W)) & 1) ? Bv : A;
            P = cmulf(P, col);
        }
        float2 cA[5], cB[5];
#pragma unroll
        for (int j = 0; j < 5; j++) {
            float4 u = Us[5 + j];
            float c = __shfl_sync(FULLM, zc, 5 + j);
            float s = __shfl_sync(FULLM, zs, 5 + j);
            cA[j] = make_float2(u.x * c + u.z * s, u.y * c + u.w * s);
            cB[j] = make_float2(u.x * s - u.z * c, u.w * c - u.y * s);
        }
        u64 Hx = pk2(cA[4].x, cB[4].x);
        u64 Hy = pk2(cA[4].y, cB[4].y);
        float2 P0 = cmulf(P, cA[0]);
        float2 P1 = cmulf(P, cB[0]);
        u64 B0x = fma2(bc2(P0.x), Hx, mul2(bc2(-P0.y), Hy));
        u64 B0y = fma2(bc2(P0.x), Hy, mul2(bc2(P0.y),  Hx));
        u64 B1x = fma2(bc2(P1.x), Hx, mul2(bc2(-P1.y), Hy));
        u64 B1y = fma2(bc2(P1.x), Hy, mul2(bc2(P1.y),  Hx));
        float2 F[8];
        F[0] = cA[3];  F[1] = cB[3];
        {
            float2 G[4];
            G[0] = cmulf(cA[2], F[0]);  G[1] = cmulf(cA[2], F[1]);
            G[2] = cmulf(cB[2], F[0]);  G[3] = cmulf(cB[2], F[1]);
            F[0] = cmulf(cA[1], G[0]);  F[1] = cmulf(cA[1], G[1]);
            F[2] = cmulf(cA[1], G[2]);  F[3] = cmulf(cA[1], G[3]);
            F[4] = cmulf(cB[1], G[0]);  F[5] = cmulf(cB[1], G[1]);
            F[6] = cmulf(cB[1], G[2]);  F[7] = cmulf(cB[1], G[3]);
        }
#pragma unroll
        for (int m = 0; m < 16; m++) {
            float2 f = F[((m & 4) ? 4 : 0) | ((m & 2) ? 2 : 0) | (m & 1)];
            u64 bx = (m & 8) ? B1x : B0x;
            u64 by = (m & 8) ? B1y : B0y;
            u64 fx = bc2(f.x), fy = bc2(f.y), fyn = bc2(-f.y);
            pX[m] = fma2(fx, bx, mul2(fyn, by));
            pY[m] = fma2(fx, by, mul2(fy, bx));
        }
    }

    // ======= A1 diagonal, then Ry layer 1 (once-permuted masks) =============
    apply_diag(pX, pY, DgA4, lane);
    {
        float2 r;
        r = RYp[0]; lane_gateR(pX, pY, 0b11000, (lane >> 4) & 1,            r.x, r.y);
        r = RYp[1]; lane_gateR(pX, pY, 0b01100, __popc(lane & 0b11000) & 1, r.x, r.y);
        r = RYp[2]; lane_gateR(pX, pY, 0b00110, __popc(lane & 0b11100) & 1, r.x, r.y);
        r = RYp[3]; lane_gateR(pX, pY, 0b00011, __popc(lane & 0b11110) & 1, r.x, r.y);
        r = RYp[4]; cross_gateR<8>(pX, pY, 0b00001, pl,                     r.x, r.y);
        r = RYp[5]; reg_gateR<0b1100, 0b0000>(pX, pY, pl,                   r.x, r.y);
        r = RYp[6]; reg_gateR<0b0110, 0b1000>(pX, pY, pl,                   r.x, r.y);
        r = RYp[7]; reg_gateR<0b0011, 0b1100>(pX, pY, pl,                   r.x, r.y);
        r = RYp[8]; hcross_gateR<1, 0b1110>(pX, pY, pl,                     r.x, r.y);
        r = RYp[9]; pair_gateR<0b1111>(pX, pY, pl,                          r.x, r.y);
    }

    // ======= D diagonal, then Ry layer 2 (2-perm masks) =====================
    apply_diag(pX, pY, DgD4, lane);
    {
        float2 r;
        r = RYp[10]; lane_gateR(pX, pY, 0b10100, (lane >> 4) & 1,            r.x, r.y);
        r = RYp[11]; lane_gateR(pX, pY, 0b01010, (lane >> 3) & 1,            r.x, r.y);
        r = RYp[12]; lane_gateR(pX, pY, 0b00101, __popc(lane & 0b10100) & 1, r.x, r.y);
        r = RYp[13]; cross_gateR<8>(pX, pY, 0b00010, pl2,                    r.x, r.y);
        r = RYp[14]; cross_gateR<4>(pX, pY, 0b00001, pl3,                    r.x, r.y);
        r = RYp[15]; reg_gateR<0b1010, 0b0000>(pX, pY, pl2,                  r.x, r.y);
        r = RYp[16]; reg_gateR<0b0101, 0b0000>(pX, pY, pl3,                  r.x, r.y);
        r = RYp[17]; hcross_gateR<2, 0b1000>(pX, pY, pl2,                    r.x, r.y);
        r = RYp[18]; reg_gateR<0b0001, 0b0100>(pX, pY, pl3,                  r.x, r.y);
        r = RYp[19]; pair_gateR<0b1010>(pX, pY, pl2,                         r.x, r.y);
    }

    // ======= features: fold M^3 into signs ==================================
    const u64 Z64 = bc2(0.0f);
    u64 pt = Z64, c4 = Z64, c3 = Z64, c2 = Z64, c1 = Z64, c0 = Z64;
    const u64 bN1 = bc2(-1.0f);
#pragma unroll
    for (int m = 0; m < 16; m++) {
        u64 pp = fma2(pX[m], pX[m], mul2(pY[m], pY[m]));
        pt = add2(pt, pp);
        c4 = ((m >> 3) & 1)           ? fma2(pp, bN1, c4) : add2(c4, pp);
        c3 = (__popc(m & 0b1100) & 1) ? fma2(pp, bN1, c3) : add2(c3, pp);
        c2 = (__popc(m & 0b0110) & 1) ? fma2(pp, bN1, c2) : add2(c2, pp);
        c1 = (__popc(m & 0b0011) & 1) ? fma2(pp, bN1, c1) : add2(c1, pp);
        c0 = (__popc(m & 0b1001) & 1) ? fma2(pp, bN1, c0) : add2(c0, pp);
    }
    float lo, hi, ptot, A5, A6, A7, A8, A9;
    up2(pt, lo, hi);  ptot = lo + hi;
    up2(c4, lo, hi);  A5 = lo + hi;
    up2(c3, lo, hi);  A6 = lo + hi;
    up2(c2, lo, hi);  A7 = lo + hi;
    up2(c1, lo, hi);  A8 = lo + hi;
    up2(c0, lo, hi);  A9 = lo - hi;

    float g0 = (__popc(lane & 0b10000) & 1) ? -ptot : ptot;
    float g1 = (__popc(lane & 0b11000) & 1) ? -ptot : ptot;
    float g2 = (__popc(lane & 0b01100) & 1) ? -ptot : ptot;
    float g3 = (__popc(lane & 0b00110) & 1) ? -ptot : ptot;
    float g4 = (__popc(lane & 0b10011) & 1) ? -ptot : ptot;
    float g5 = (__popc(lane & 0b11001) & 1) ? -A5 : A5;
    float g6 = (__popc(lane & 0b01100) & 1) ? -A6 : A6;
    float g7 = (__popc(lane & 0b00110) & 1) ? -A7 : A7;
    float g8 = (__popc(lane & 0b10011) & 1) ? -A8 : A8;
    float g9 = (__popc(lane & 0b11001) & 1) ? -A9 : A9;

    u64 r0 = pk2(g0, g5), r1 = pk2(g1, g6), r2 = pk2(g2, g7);
    u64 r3 = pk2(g3, g8), r4 = pk2(g4, g9);
#pragma unroll
    for (int o = 16; o > 0; o >>= 1) {
        r0 = add2(r0, shflx2(r0, o));
        r1 = add2(r1, shflx2(r1, o));
        r2 = add2(r2, shflx2(r2, o));
        r3 = add2(r3, shflx2(r3, o));
        r4 = add2(r4, shflx2(r4, o));
    }
    float g[NQ];
    up2(r0, g[0], g[5]);  up2(r1, g[1], g[6]);  up2(r2, g[2], g[7]);
    up2(r3, g[3], g[8]);  up2(r4, g[4], g[9]);

    // ======= MLP 10 -> 32 -> 16 -> 1 ========================================
    float a1 = b1[lane];
#pragma unroll
    for (int i = 0; i < NQ; i++) a1 += g[i] * W1[i * 32 + lane];
    float h1v = tanhf(a1);

    const int j  = lane & 15;
    const int i0 = (lane >> 4) << 4;
    float a2 = 0.5f * b2[j];
#pragma unroll
    for (int i = 0; i < 16; i++) {
        float h = __shfl_sync(FULLM, h1v, i0 + i);
        a2 += h * W2[(i0 + i) * 16 + j];
    }
    a2 += __shfl_xor_sync(FULLM, a2, 16);
    float h2v = tanhf(a2);

    float a3 = b3[0];
#pragma unroll
    for (int i = 0; i < 16; i++)
        a3 += __shfl_sync(FULLM, h2v, i) * W3[i];

    if (lane == 0) {
        float sg = 1.0f / (1.0f + __expf(-a3));
        out[b] = sg * 0.2f - 0.1f;
    }
}

extern "C" void kernel_launch(void* const* d_in, const int* in_sizes, int n_in,
                              void* d_out, int out_size) {
    const float* z       = (const float*)d_in[0];
    const float* weights = (const float*)d_in[1];
    const float* W1      = (const float*)d_in[2];
    const float* b1      = (const float*)d_in[3];
    const float* W2      = (const float*)d_in[4];
    const float* b2      = (const float*)d_in[5];
    const float* W3      = (const float*)d_in[6];
    const float* b3      = (const float*)d_in[7];
    float* out           = (float*)d_out;

    const int B = in_sizes[0] / NQ;                 // 4096
    const int grid = (B + WPB - 1) / WPB;
    precompute_kernel<<<1, 128>>>(weights);
    qgan_kernel<<<grid, THREADS>>>(z, W1, b1, W2, b2, W3, b3, out, B);
}

// round 13
// speedup vs baseline: 1.0862x; 1.0862x over previous
#include <cuda_runtime.h>
#include <math.h>

#define FULLM 0xffffffffu
#define NQ 10
#define WPB 4
#define THREADS (WPB * 32)

typedef unsigned long long u64;

// ---- precomputed weight-only tables (built once per launch) -----------------
__device__ float4 g_Us[NQ];       // layer-0 U (u00.x,u00.y,u01.x,u01.y)
__device__ float2 g_RYp[2 * NQ];  // (cos b/2, sin b/2) layers 1,2
__device__ float4 g_DgA[512];     // diag Rz(a1)
__device__ float4 g_DgD[512];     // diag Rz(c1)*Rz(a2)

// ---- f32x2 packed helpers --------------------------------------------------
__device__ __forceinline__ u64 bc2(float s) {
    u64 d; unsigned r = __float_as_uint(s);
    asm("mov.b64 %0, {%1, %1};" : "=l"(d) : "r"(r));
    return d;
}
__device__ __forceinline__ u64 pk2(float lo, float hi) {
    u64 d; unsigned a = __float_as_uint(lo), b = __float_as_uint(hi);
    asm("mov.b64 %0, {%1, %2};" : "=l"(d) : "r"(a), "r"(b));
    return d;
}
__device__ __forceinline__ void up2(u64 a, float& lo, float& hi) {
    unsigned l, h;
    asm("mov.b64 {%0, %1}, %2;" : "=r"(l), "=r"(h) : "l"(a));
    lo = __uint_as_float(l); hi = __uint_as_float(h);
}
__device__ __forceinline__ u64 fma2(u64 a, u64 b, u64 c) {
    u64 d;
    asm("fma.rn.f32x2 %0, %1, %2, %3;" : "=l"(d) : "l"(a), "l"(b), "l"(c));
    return d;
}
__device__ __forceinline__ u64 mul2(u64 a, u64 b) {
    u64 d;
    asm("mul.rn.f32x2 %0, %1, %2;" : "=l"(d) : "l"(a), "l"(b));
    return d;
}
__device__ __forceinline__ u64 add2(u64 a, u64 b) {
    u64 d;
    asm("add.rn.f32x2 %0, %1, %2;" : "=l"(d) : "l"(a), "l"(b));
    return d;
}
__device__ __forceinline__ u64 swp2(u64 a) {
    unsigned l, h;
    asm("mov.b64 {%0, %1}, %2;" : "=r"(l), "=r"(h) : "l"(a));
    u64 d;
    asm("mov.b64 %0, {%1, %2};" : "=l"(d) : "r"(h), "r"(l));
    return d;
}
__device__ __forceinline__ u64 shflx2(u64 a, int mask) {
    unsigned l, h;
    asm("mov.b64 {%0, %1}, %2;" : "=r"(l), "=r"(h) : "l"(a));
    l = __shfl_xor_sync(FULLM, l, mask);
    h = __shfl_xor_sync(FULLM, h, mask);
    u64 d;
    asm("mov.b64 %0, {%1, %2};" : "=l"(d) : "r"(l), "r"(h));
    return d;
}
__device__ __forceinline__ float2 cmulf(float2 a, float2 b) {
    return make_float2(a.x * b.x - a.y * b.y, a.x * b.y + a.y * b.x);
}

// ---- Ry gate primitives (real rotations) ------------------------------------
// State: amp index s = (lane<<5)|(m<<1)|h ; pX/pY hold (h=0,h=1) packed.

__device__ __forceinline__ void lane_gateR(u64 pX[16], u64 pY[16],
                                           int xorMask, bool hi,
                                           float cb, float sb) {
    const float t = hi ? sb : -sb;
    const u64 C = bc2(cb), T = bc2(t);
#pragma unroll
    for (int m = 0; m < 16; m++) {
        u64 bx = shflx2(pX[m], xorMask), by = shflx2(pY[m], xorMask);
        pX[m] = fma2(C, pX[m], mul2(T, bx));
        pY[m] = fma2(C, pY[m], mul2(T, by));
    }
}

template<int MXOR>
__device__ __forceinline__ void cross_gateR(u64 pX[16], u64 pY[16],
                                            int laneXor, bool hi,
                                            float cb, float sb) {
    const float t = hi ? sb : -sb;
    const u64 C = bc2(cb), T = bc2(t);
#pragma unroll
    for (int m0 = 0; m0 < 16; m0++) {
        if (m0 & MXOR) continue;
        const int m1 = m0 | MXOR;
        u64 b0x = shflx2(pX[m1], laneXor), b0y = shflx2(pY[m1], laneXor);
        u64 b1x = shflx2(pX[m0], laneXor), b1y = shflx2(pY[m0], laneXor);
        pX[m0] = fma2(C, pX[m0], mul2(T, b0x));
        pY[m0] = fma2(C, pY[m0], mul2(T, b0y));
        pX[m1] = fma2(C, pX[m1], mul2(T, b1x));
        pY[m1] = fma2(C, pY[m1], mul2(T, b1y));
    }
}

template<int MXOR> struct Anch {
    static const int v = (MXOR >= 8) ? 8 : (MXOR >= 4) ? 4 : (MXOR >= 2) ? 2 : 1;
};

template<int MXOR, int CLS>
__device__ __forceinline__ void reg_gateR(u64 pX[16], u64 pY[16], bool sb_sel,
                                          float cb, float sbv) {
    const float x1 = sb_sel ? sbv : -sbv;
    const u64 C = bc2(cb), T = bc2(x1), Tn = bc2(-x1);
#pragma unroll
    for (int mA = 0; mA < 16; mA++) {
        if (mA & Anch<MXOR>::v) continue;
        const int mB = mA ^ MXOR;
        const bool cls = __popc(mA & CLS) & 1;
        const u64 tp = cls ? Tn : T;
        const u64 tn = cls ? T : Tn;
        u64 Ax = pX[mA], Ay = pY[mA], Bx = pX[mB], By = pY[mB];
        pX[mA] = fma2(C, Ax, mul2(tp, Bx));
        pY[mA] = fma2(C, Ay, mul2(tp, By));
        pX[mB] = fma2(C, Bx, mul2(tn, Ax));
        pY[mB] = fma2(C, By, mul2(tn, Ay));
    }
}

template<int MXOR, int CLS>
__device__ __forceinline__ void hcross_gateR(u64 pX[16], u64 pY[16], bool sb_sel,
                                             float cb, float sbv) {
    const float x1 = sb_sel ? sbv : -sbv;
    const u64 C = bc2(cb), T = bc2(x1), Tn = bc2(-x1);
#pragma unroll
    for (int mA = 0; mA < 16; mA++) {
        if (mA & Anch<MXOR>::v) continue;
        const int mB = mA ^ MXOR;
        const bool cls = __popc(mA & CLS) & 1;
        const u64 tp = cls ? Tn : T;
        const u64 tn = cls ? T : Tn;
        u64 Ax = pX[mA], Ay = pY[mA];
        u64 Bx = swp2(pX[mB]), By = swp2(pY[mB]);
        u64 nBx = fma2(C, Bx, mul2(tn, Ax));
        u64 nBy = fma2(C, By, mul2(tn, Ay));
        pX[mA] = fma2(C, Ax, mul2(tp, Bx));
        pY[mA] = fma2(C, Ay, mul2(tp, By));
        pX[mB] = swp2(nBx); pY[mB] = swp2(nBy);
    }
}

template<int CLS>
__device__ __forceinline__ void pair_gateR(u64 pX[16], u64 pY[16], bool sb_sel,
                                           float cb, float sbv) {
    const float x1 = sb_sel ? sbv : -sbv;
    const u64 C = bc2(cb);
    const u64 OX = pk2(x1, -x1), OXn = pk2(-x1, x1);
#pragma unroll
    for (int m = 0; m < 16; m++) {
        const bool s = __popc(m & CLS) & 1;
        u64 ox = s ? OXn : OX;
        u64 sx = swp2(pX[m]), sy = swp2(pY[m]);
        pX[m] = fma2(C, pX[m], mul2(ox, sx));
        pY[m] = fma2(C, pY[m], mul2(ox, sy));
    }
}

// diag entry: float4 (c0,s0,c1,s1) at index (m<<5)|lane
__device__ __forceinline__ void apply_diag(u64 pX[16], u64 pY[16],
                                           const float4* Dg, int lane) {
#pragma unroll
    for (int m = 0; m < 16; m++) {
        float4 f = Dg[(m << 5) | lane];
        u64 kx = pk2(f.x, f.z), ky = pk2(f.y, f.w), kyn = pk2(-f.y, -f.w);
        u64 nx = fma2(kx, pX[m], mul2(kyn, pY[m]));
        u64 ny = fma2(kx, pY[m], mul2(ky,  pX[m]));
        pX[m] = nx; pY[m] = ny;
    }
}

// ======= parallel precompute: 16 blocks x 128 threads, 1 diag entry each =====
__global__ __launch_bounds__(128)
void precompute_kernel(const float* __restrict__ weights)
{
    __shared__ float thA1[10], thC1[10], thA2[10];
    __shared__ float LUT[6][32];

    const int tid = threadIdx.x;
    const int blk = blockIdx.x;

    // per-block: half-angle tables (cheap)
    if (tid < 30) {
        int arr = tid / 10, k = tid % 10; int w = 9 - k;
        float v = (arr == 0) ? weights[(10 + w) * 3 + 0]
                : (arr == 1) ? weights[(10 + w) * 3 + 2]
                             : weights[(20 + w) * 3 + 0];
        float* dst = (arr == 0) ? thA1 : (arr == 1) ? thC1 : thA2;
        dst[k] = 0.5f * v;
    }
    // block 0 additionally fills the small gate-param tables
    if (blk == 0) {
        if (tid >= 64 && tid < 64 + NQ) {
            int i = tid - 64;
            float a  = weights[i * 3 + 0];
            float bb = weights[i * 3 + 1];
            float c  = weights[i * 3 + 2];
            float cb, sb;  __sincosf(0.5f * bb, &sb, &cb);
            float capc, sapc, camc, samc;
            __sincosf(0.5f * (a + c), &sapc, &capc);
            __sincosf(0.5f * (a - c), &samc, &camc);
            g_Us[i] = make_float4(cb * capc, -cb * sapc, -sb * camc, -sb * samc);
        }
        if (tid >= 96 && tid < 116) {
            int g = tid - 96; int l = g / 10, w = g % 10;
            float bb = weights[((l + 1) * 10 + w) * 3 + 1];
            float sbv, cbv; __sincosf(0.5f * bb, &sbv, &cbv);
            g_RYp[g] = make_float2(cbv, sbv);
        }
    }
    __syncthreads();

    // per-block LUTs (192 entries, ~1.5/thread)
    for (int v = tid; v < 192; v += 128) {
        int tbl = v >> 5, idx = v & 31;
        const float* th = (tbl < 2) ? thA1 : (tbl < 4) ? thC1 : thA2;
        int base = (tbl & 1) * 5;
        float phi = 0.0f;
#pragma unroll
        for (int k = 0; k < 5; k++)
            phi += ((idx >> k) & 1) ? th[base + k] : -th[base + k];
        LUT[tbl][idx] = phi;
    }
    __syncthreads();

    // one diag entry per thread
    {
        int e = blk * 128 + tid;          // 0..2047
        int s = e & 1023;
        int t = s;
        t ^= t >> 1;  t ^= t >> 2;  t ^= t >> 4;  t ^= t >> 8;
        float phi;
        if (e < 1024) {
            phi = LUT[0][t & 31] + LUT[1][t >> 5];
        } else {
            int u = s;
            u ^= u >> 2;  u ^= u >> 4;  u ^= u >> 8;
            phi = LUT[2][t & 31] + LUT[3][t >> 5]
                + LUT[4][u & 31] + LUT[5][u >> 5];
        }
        float sn, cs; __sincosf(phi, &sn, &cs);
        int slot = (((s >> 1) & 15) << 5) | (s >> 5);
        float* dst = (float*)((e < 1024 ? g_DgA : g_DgD) + slot);
        dst[(s & 1) * 2 + 0] = cs;
        dst[(s & 1) * 2 + 1] = sn;
    }
}

// ======= main kernel =========================================================
__global__ __launch_bounds__(THREADS, 5)
void qgan_kernel(const float* __restrict__ z,
                 const float* __restrict__ W1, const float* __restrict__ b1,
                 const float* __restrict__ W2, const float* __restrict__ b2,
                 const float* __restrict__ W3, const float* __restrict__ b3,
                 float* __restrict__ out, int B)
{
    __shared__ float4 Us[NQ];
    __shared__ float2 RYp[2 * NQ];
    __shared__ float4 DgA4[512];
    __shared__ float4 DgD4[512];

    const int tid  = threadIdx.x;
    const int lane = tid & 31;
    const int wix  = tid >> 5;
    const int b    = blockIdx.x * WPB + wix;

    // copy precomputed tables into smem
#pragma unroll
    for (int i = tid; i < 512; i += THREADS) {
        DgA4[i] = g_DgA[i];
        DgD4[i] = g_DgD[i];
    }
    if (tid < NQ)                     Us[tid] = g_Us[tid];
    else if (tid >= 32 && tid < 52)   RYp[tid - 32] = g_RYp[tid - 32];
    __syncthreads();

    if (b >= B) return;

    float zc = 1.0f, zs = 0.0f;
    if (lane < NQ) {
        float zv = z[b * NQ + lane];
        zv = fminf(fmaxf(zv, -1.0f), 1.0f);
        __sincosf(0.5f * zv, &zs, &zc);
    }

    const bool pl  = __popc(lane) & 1;
    const bool pl2 = __popc(lane & 0b01010) & 1;
    const bool pl3 = __popc(lane & 0b10101) & 1;

    u64 pX[16], pY[16];

    // ======= layer 0 on |0..0>: product-state construction ==================
    {
        float2 P = make_float2(1.0f, 0.0f);
#pragma unroll
        for (int W = 0; W < 5; W++) {
            float4 u = Us[W];
            float c = __shfl_sync(FULLM, zc, W);
            float s = __shfl_sync(FULLM, zs, W);
            float2 A  = make_float2(u.x * c + u.z * s, u.y * c + u.w * s);
            float2 Bv = make_float2(u.x * s - u.z * c, u.w * c - u.y * s);
            float2 col = ((lane >> (4 - W)) & 1) ? Bv : A;
            P = cmulf(P, col);
        }
        float2 cA[5], cB[5];
#pragma unroll
        for (int j = 0; j < 5; j++) {
            float4 u = Us[5 + j];
            float c = __shfl_sync(FULLM, zc, 5 + j);
            float s = __shfl_sync(FULLM, zs, 5 + j);
            cA[j] = make_float2(u.x * c + u.z * s, u.y * c + u.w * s);
            cB[j] = make_float2(u.x * s - u.z * c, u.w * c - u.y * s);
        }
        u64 Hx = pk2(cA[4].x, cB[4].x);
        u64 Hy = pk2(cA[4].y, cB[4].y);
        float2 P0 = cmulf(P, cA[0]);
        float2 P1 = cmulf(P, cB[0]);
        u64 B0x = fma2(bc2(P0.x), Hx, mul2(bc2(-P0.y), Hy));
        u64 B0y = fma2(bc2(P0.x), Hy, mul2(bc2(P0.y),  Hx));
        u64 B1x = fma2(bc2(P1.x), Hx, mul2(bc2(-P1.y), Hy));
        u64 B1y = fma2(bc2(P1.x), Hy, mul2(bc2(P1.y),  Hx));
        float2 F[8];
        F[0] = cA[3];  F[1] = cB[3];
        {
            float2 G[4];
            G[0] = cmulf(cA[2], F[0]);  G[1] = cmulf(cA[2], F[1]);
            G[2] = cmulf(cB[2], F[0]);  G[3] = cmulf(cB[2], F[1]);
            F[0] = cmulf(cA[1], G[0]);  F[1] = cmulf(cA[1], G[1]);
            F[2] = cmulf(cA[1], G[2]);  F[3] = cmulf(cA[1], G[3]);
            F[4] = cmulf(cB[1], G[0]);  F[5] = cmulf(cB[1], G[1]);
            F[6] = cmulf(cB[1], G[2]);  F[7] = cmulf(cB[1], G[3]);
        }
#pragma unroll
        for (int m = 0; m < 16; m++) {
            float2 f = F[((m & 4) ? 4 : 0) | ((m & 2) ? 2 : 0) | (m & 1)];
            u64 bx = (m & 8) ? B1x : B0x;
            u64 by = (m & 8) ? B1y : B0y;
            u64 fx = bc2(f.x), fy = bc2(f.y), fyn = bc2(-f.y);
            pX[m] = fma2(fx, bx, mul2(fyn, by));
            pY[m] = fma2(fx, by, mul2(fy, bx));
        }
    }

    // ======= A1 diagonal, then Ry layer 1 (once-permuted masks) =============
    apply_diag(pX, pY, DgA4, lane);
    {
        float2 r;
        r = RYp[0]; lane_gateR(pX, pY, 0b11000, (lane >> 4) & 1,            r.x, r.y);
        r = RYp[1]; lane_gateR(pX, pY, 0b01100, __popc(lane & 0b11000) & 1, r.x, r.y);
        r = RYp[2]; lane_gateR(pX, pY, 0b00110, __popc(lane & 0b11100) & 1, r.x, r.y);
        r = RYp[3]; lane_gateR(pX, pY, 0b00011, __popc(lane & 0b11110) & 1, r.x, r.y);
        r = RYp[4]; cross_gateR<8>(pX, pY, 0b00001, pl,                     r.x, r.y);
        r = RYp[5]; reg_gateR<0b1100, 0b0000>(pX, pY, pl,                   r.x, r.y);
        r = RYp[6]; reg_gateR<0b0110, 0b1000>(pX, pY, pl,                   r.x, r.y);
        r = RYp[7]; reg_gateR<0b0011, 0b1100>(pX, pY, pl,                   r.x, r.y);
        r = RYp[8]; hcross_gateR<1, 0b1110>(pX, pY, pl,                     r.x, r.y);
        r = RYp[9]; pair_gateR<0b1111>(pX, pY, pl,                          r.x, r.y);
    }

    // ======= D diagonal, then Ry layer 2 (2-perm masks) =====================
    apply_diag(pX, pY, DgD4, lane);
    {
        float2 r;
        r = RYp[10]; lane_gateR(pX, pY, 0b10100, (lane >> 4) & 1,            r.x, r.y);
        r = RYp[11]; lane_gateR(pX, pY, 0b01010, (lane >> 3) & 1,            r.x, r.y);
        r = RYp[12]; lane_gateR(pX, pY, 0b00101, __popc(lane & 0b10100) & 1, r.x, r.y);
        r = RYp[13]; cross_gateR<8>(pX, pY, 0b00010, pl2,                    r.x, r.y);
        r = RYp[14]; cross_gateR<4>(pX, pY, 0b00001, pl3,                    r.x, r.y);
        r = RYp[15]; reg_gateR<0b1010, 0b0000>(pX, pY, pl2,                  r.x, r.y);
        r = RYp[16]; reg_gateR<0b0101, 0b0000>(pX, pY, pl3,                  r.x, r.y);
        r = RYp[17]; hcross_gateR<2, 0b1000>(pX, pY, pl2,                    r.x, r.y);
        r = RYp[18]; reg_gateR<0b0001, 0b0100>(pX, pY, pl3,                  r.x, r.y);
        r = RYp[19]; pair_gateR<0b1010>(pX, pY, pl2,                         r.x, r.y);
    }

    // ======= features: fold M^3 into signs ==================================
    const u64 Z64 = bc2(0.0f);
    u64 pt = Z64, c4 = Z64, c3 = Z64, c2 = Z64, c1 = Z64, c0 = Z64;
    const u64 bN1 = bc2(-1.0f);
#pragma unroll
    for (int m = 0; m < 16; m++) {
        u64 pp = fma2(pX[m], pX[m], mul2(pY[m], pY[m]));
        pt = add2(pt, pp);
        c4 = ((m >> 3) & 1)           ? fma2(pp, bN1, c4) : add2(c4, pp);
        c3 = (__popc(m & 0b1100) & 1) ? fma2(pp, bN1, c3) : add2(c3, pp);
        c2 = (__popc(m & 0b0110) & 1) ? fma2(pp, bN1, c2) : add2(c2, pp);
        c1 = (__popc(m & 0b0011) & 1) ? fma2(pp, bN1, c1) : add2(c1, pp);
        c0 = (__popc(m & 0b1001) & 1) ? fma2(pp, bN1, c0) : add2(c0, pp);
    }
    float lo, hi, ptot, A5, A6, A7, A8, A9;
    up2(pt, lo, hi);  ptot = lo + hi;
    up2(c4, lo, hi);  A5 = lo + hi;
    up2(c3, lo, hi);  A6 = lo + hi;
    up2(c2, lo, hi);  A7 = lo + hi;
    up2(c1, lo, hi);  A8 = lo + hi;
    up2(c0, lo, hi);  A9 = lo - hi;

    float g0 = (__popc(lane & 0b10000) & 1) ? -ptot : ptot;
    float g1 = (__popc(lane & 0b11000) & 1) ? -ptot : ptot;
    float g2 = (__popc(lane & 0b01100) & 1) ? -ptot : ptot;
    float g3 = (__popc(lane & 0b00110) & 1) ? -ptot : ptot;
    float g4 = (__popc(lane & 0b10011) & 1) ? -ptot : ptot;
    float g5 = (__popc(lane & 0b11001) & 1) ? -A5 : A5;
    float g6 = (__popc(lane & 0b01100) & 1) ? -A6 : A6;
    float g7 = (__popc(lane & 0b00110) & 1) ? -A7 : A7;
    float g8 = (__popc(lane & 0b10011) & 1) ? -A8 : A8;
    float g9 = (__popc(lane & 0b11001) & 1) ? -A9 : A9;

    u64 r0 = pk2(g0, g5), r1 = pk2(g1, g6), r2 = pk2(g2, g7);
    u64 r3 = pk2(g3, g8), r4 = pk2(g4, g9);
#pragma unroll
    for (int o = 16; o > 0; o >>= 1) {
        r0 = add2(r0, shflx2(r0, o));
        r1 = add2(r1, shflx2(r1, o));
        r2 = add2(r2, shflx2(r2, o));
        r3 = add2(r3, shflx2(r3, o));
        r4 = add2(r4, shflx2(r4, o));
    }
    float g[NQ];
    up2(r0, g[0], g[5]);  up2(r1, g[1], g[6]);  up2(r2, g[2], g[7]);
    up2(r3, g[3], g[8]);  up2(r4, g[4], g[9]);

    // ======= MLP 10 -> 32 -> 16 -> 1 ========================================
    float a1 = b1[lane];
#pragma unroll
    for (int i = 0; i < NQ; i++) a1 += g[i] * W1[i * 32 + lane];
    float h1v = tanhf(a1);

    const int j  = lane & 15;
    const int i0 = (lane >> 4) << 4;
    float a2 = 0.5f * b2[j];
#pragma unroll
    for (int i = 0; i < 16; i++) {
        float h = __shfl_sync(FULLM, h1v, i0 + i);
        a2 += h * W2[(i0 + i) * 16 + j];
    }
    a2 += __shfl_xor_sync(FULLM, a2, 16);
    float h2v = tanhf(a2);

    float a3 = b3[0];
#pragma unroll
    for (int i = 0; i < 16; i++)
        a3 += __shfl_sync(FULLM, h2v, i) * W3[i];

    if (lane == 0) {
        float sg = 1.0f / (1.0f + __expf(-a3));
        out[b] = sg * 0.2f - 0.1f;
    }
}

extern "C" void kernel_launch(void* const* d_in, const int* in_sizes, int n_in,
                              void* d_out, int out_size) {
    const float* z       = (const float*)d_in[0];
    const float* weights = (const float*)d_in[1];
    const float* W1      = (const float*)d_in[2];
    const float* b1      = (const float*)d_in[3];
    const float* W2      = (const float*)d_in[4];
    const float* b2      = (const float*)d_in[5];
    const float* W3      = (const float*)d_in[6];
    const float* b3      = (const float*)d_in[7];
    float* out           = (float*)d_out;

    const int B = in_sizes[0] / NQ;                 // 4096
    const int grid = (B + WPB - 1) / WPB;
    precompute_kernel<<<16, 128>>>(weights);
    qgan_kernel<<<grid, THREADS>>>(z, W1, b1, W2, b2, W3, b3, out, B);
}